// round 15
// baseline (speedup 1.0000x reference)
#include <cuda_runtime.h>
#include <cuda_bf16.h>

// Problem constants
#define PB   32
#define PT   8192
#define PC   3
#define PLS  32
#define PNS  256
#define PW   (PT - PLS + 1)        // 8161

#define KF      96                 // K = LS*C
#define KPAD    128                // global K row pad (u16 elements)
#define NTILE   64                 // windows per item
#define WTILES  (PT / NTILE)       // 128
#define NITEMS  (PB * WTILES)      // 4096
#define THREADS 256

#define FLATN   (PT * PC)          // 24576
#define PTF     (FLATN + 96)       // phase-array padded length (24672)

#define BSTR    208                // B row stride bytes (104 bf16, conflict-free)
#define BTERM   13312              // 64 rows * 208
#define BUFSZ   26624              // hi + lo
#define NBUF    4
#define SM_A2   (NBUF * BUFSZ)     // 106496
#define SM_TOT  (SM_A2 + NBUF * 256)  // 107520

typedef unsigned int u32;
typedef unsigned short u16;
typedef unsigned long long u64;

// Device scratch (allocations forbidden)
__device__ __align__(16) u16 g_xhi[8 * PB * PTF];   // 8 phase-shifted flat bf16 hi
__device__ __align__(16) u16 g_xlo[8 * PB * PTF];   // 8 phase-shifted flat bf16 lo
__device__ __align__(16) u16 g_khi[PNS * KPAD];     // bf16(-2k) hi
__device__ __align__(16) u16 g_klo[PNS * KPAD];     // bf16(-2k) lo
__device__ float g_d2[PB * PT];
__device__ float g_a2[PB * PT];                     // padded; >=PW poisoned
__device__ float g_k2[PNS];
__device__ u32   g_amin[PB * PNS];
__device__ u32   g_done;

// ---------------------------------------------------------------------------
__device__ __forceinline__ u32 smem_u32(const void* p) {
    u32 a; asm("{ .reg .u64 t; cvta.to.shared.u64 t, %1; cvt.u32.u64 %0, t; }"
               : "=r"(a) : "l"(p));
    return a;
}
__device__ __forceinline__ u32 fenc(float f) {
    u32 u = __float_as_uint(f);
    return (u & 0x80000000u) ? ~u : (u | 0x80000000u);
}
__device__ __forceinline__ float fdec(u32 u) {
    u32 b = (u & 0x80000000u) ? (u & 0x7FFFFFFFu) : ~u;
    return __uint_as_float(b);
}
__device__ __forceinline__ void split2(float v0, float v1, u32& hi, u32& lo) {
    __nv_bfloat16 h0 = __float2bfloat16(v0);
    __nv_bfloat16 h1 = __float2bfloat16(v1);
    __nv_bfloat16 l0 = __float2bfloat16(v0 - __bfloat162float(h0));
    __nv_bfloat16 l1 = __float2bfloat16(v1 - __bfloat162float(h1));
    hi = (u32)__bfloat16_as_ushort(h0) | ((u32)__bfloat16_as_ushort(h1) << 16);
    lo = (u32)__bfloat16_as_ushort(l0) | ((u32)__bfloat16_as_ushort(l1) << 16);
}

#define LDSM4(r0, r1, r2, r3, addr) \
    asm volatile("ldmatrix.sync.aligned.m8n8.x4.shared.b16 {%0,%1,%2,%3}, [%4];" \
        : "=r"(r0), "=r"(r1), "=r"(r2), "=r"(r3) : "r"(addr))

#define MMA16816(d, a0, a1, a2, a3, b0, b1) \
    asm volatile("mma.sync.aligned.m16n8k16.row.col.f32.bf16.bf16.f32 " \
        "{%0,%1,%2,%3}, {%4,%5,%6,%7}, {%8,%9}, {%0,%1,%2,%3};" \
        : "+f"((d)[0]), "+f"((d)[1]), "+f"((d)[2]), "+f"((d)[3]) \
        : "r"(a0), "r"(a1), "r"(a2), "r"(a3), "r"(b0), "r"(b1))

#define CPASYNC16(dst, src) \
    asm volatile("cp.async.cg.shared.global [%0], [%1], 16;" :: "r"(dst), "l"(src))
#define CPASYNC4(dst, src) \
    asm volatile("cp.async.ca.shared.global [%0], [%1], 4;" :: "r"(dst), "l"(src))

// ---------------------------------------------------------------------------
// prep1: d2, K(-2k) hi/lo, amin init, warp-parallel k2, done counter
__global__ void prep1_kernel(const float* __restrict__ data,
                             const float* __restrict__ ker) {
    int i = blockIdx.x * blockDim.x + threadIdx.x;
    if (i < PB * PT) {
        const float* p = data + (size_t)i * 3;
        float x0 = p[0], x1 = p[1], x2 = p[2];
        g_d2[i] = x0 * x0 + x1 * x1 + x2 * x2;
    }
    if (i < PNS * PLS) {
        int s = i / PLS, l = i % PLS;
        #pragma unroll
        for (int c = 0; c < 3; c++) {
            float v = -2.f * ker[i * 3 + c];
            __nv_bfloat16 hi = __float2bfloat16(v);
            __nv_bfloat16 lo = __float2bfloat16(v - __bfloat162float(hi));
            g_khi[s * KPAD + l * 3 + c] = __bfloat16_as_ushort(hi);
            g_klo[s * KPAD + l * 3 + c] = __bfloat16_as_ushort(lo);
        }
    }
    if (i < PB * PNS) g_amin[i] = 0xFFFFFFFFu;
    if (i < PNS * 32) {
        int s = i >> 5, lane = i & 31;
        const float* kp = ker + s * KF + lane * 3;
        float v0 = kp[0], v1 = kp[1], v2 = kp[2];
        float k2 = v0 * v0 + v1 * v1 + v2 * v2;
        #pragma unroll
        for (int off = 16; off > 0; off >>= 1)
            k2 += __shfl_xor_sync(0xFFFFFFFFu, k2, off);
        if (lane == 0) g_k2[s] = k2;
    }
    if (i == 0) g_done = 0u;
}

// prep2: phase arrays (x4 vectorized: one uint4 = 8 elements/thread) + a2
__global__ void prep2_kernel(const float* __restrict__ data) {
    const int HP4 = PTF / 8;            // uint4 per (p,b) = 3084
    int j = blockIdx.x * blockDim.x + threadIdx.x;
    if (j < 8 * PB * HP4) {
        int i4 = j % HP4;
        int r  = j / HP4;               // = p*PB + b
        int b  = r % PB;
        int p  = r / PB;
        int e0 = 8 * i4 + p;
        const float* db = data + (size_t)b * FLATN;
        float v[8];
        #pragma unroll
        for (int m = 0; m < 8; m++) {
            int em = e0 + m;
            v[m] = (em < FLATN) ? __ldg(db + em) : 0.f;
        }
        uint4 H, L;
        split2(v[0], v[1], H.x, L.x);
        split2(v[2], v[3], H.y, L.y);
        split2(v[4], v[5], H.z, L.z);
        split2(v[6], v[7], H.w, L.w);
        ((uint4*)g_xhi)[r * HP4 + i4] = H;
        ((uint4*)g_xlo)[r * HP4 + i4] = L;
    }
    if (j < PB * PT) {
        int b = j / PT, w = j % PT;
        float s = 1e30f;
        if (w < PW) {
            const float* d = g_d2 + b * PT + w;
            s = 0.f;
            #pragma unroll
            for (int q = 0; q < PLS; q++) s += d[q];
        }
        g_a2[j] = s;
    }
}

// ---------------------------------------------------------------------------
// issue cp.async group for one item: 2 terms x 64 rows x 12 quads + a2
__device__ __forceinline__ void issue_item(u32 sbase, int buf, int b, int w0) {
    int tid = threadIdx.x;
    u32 bufbase = sbase + (u32)buf * BUFSZ;
    #pragma unroll
    for (int rep = 0; rep < 6; rep++) {
        int c = tid + rep * 256;            // 0..1535
        int term = c / 768;
        int cc = c - term * 768;
        int row = cc / 12, q = cc - row * 12;
        int E = 3 * (w0 + row), p = E & 7;
        const u16* src = (term ? g_xlo : g_xhi)
                         + (size_t)(p * PB + b) * PTF + (E - p) + q * 8;
        u32 dst = bufbase + (u32)term * BTERM + (u32)row * BSTR + (u32)q * 16;
        CPASYNC16(dst, src);
    }
    if (tid < NTILE) {
        const float* src = g_a2 + (size_t)b * PT + w0 + tid;
        u32 dst = sbase + SM_A2 + (u32)buf * 256 + (u32)tid * 4;
        CPASYNC4(dst, src);
    }
    asm volatile("cp.async.commit_group;" ::: "memory");
}

// ---------------------------------------------------------------------------
// Main: R12 structure; per-kstep MMAs reordered into 3 passes of 16
// independent HMMAs (max RAW spacing on accumulators).
__global__ __launch_bounds__(THREADS, 1) void mma_main_kernel(
        float* __restrict__ out) {
    extern __shared__ __align__(16) char smem[];
    u32 sbase = smem_u32(smem);
    int tid  = threadIdx.x;
    int lane = tid & 31;
    int warp = tid >> 5;                 // 0..7 -> M rows warp*32..+31
    int g    = lane >> 2;                // 0..7
    int tg   = lane & 3;                 // 0..3

    // ---- Persistent A fragments (mma layout), loaded once via LDG
    u32 Ah[48], Al[48];                  // [ks*8 + mt*4 + q]
    {
        int r0 = warp * 32 + g;
        #pragma unroll
        for (int ks = 0; ks < 6; ks++) {
            #pragma unroll
            for (int mt = 0; mt < 2; mt++) {
                int r = r0 + mt * 16;
                int col = ks * 16 + tg * 2;
                const u16* ph = g_khi + (size_t)r * KPAD + col;
                const u16* pl = g_klo + (size_t)r * KPAD + col;
                int o = ks * 8 + mt * 4;
                Ah[o + 0] = *(const u32*)(ph);
                Ah[o + 1] = *(const u32*)(ph + 8 * KPAD);
                Ah[o + 2] = *(const u32*)(ph + 8);
                Ah[o + 3] = *(const u32*)(ph + 8 * KPAD + 8);
                Al[o + 0] = *(const u32*)(pl);
                Al[o + 1] = *(const u32*)(pl + 8 * KPAD);
                Al[o + 2] = *(const u32*)(pl + 8);
                Al[o + 3] = *(const u32*)(pl + 8 * KPAD + 8);
            }
        }
    }

    // ldmatrix B per-thread offset (proven mapping)
    int ti = lane >> 3, l8 = lane & 7;
    u32 boff = (u32)((((ti >> 1) * 8 + l8) * BSTR) + (ti & 1) * 16);

    // ---- contiguous item range for this CTA
    int G    = gridDim.x;
    int base = NITEMS / G, rem = NITEMS % G;
    int cta  = blockIdx.x;
    int lo   = cta * base + (cta < rem ? cta : rem);
    int cnt  = base + (cta < rem ? 1 : 0);

    // ---- prologue: prefetch up to 2 items
    if (cnt > 0) issue_item(sbase, 0, lo >> 7,        (lo & 127) * NTILE);
    if (cnt > 1) issue_item(sbase, 1, (lo + 1) >> 7, ((lo + 1) & 127) * NTILE);

    float mm[2][2];
    mm[0][0] = mm[0][1] = mm[1][0] = mm[1][1] = 3.4e38f;

    for (int k = 0; k < cnt; k++) {
        int u  = lo + k;
        int b  = u >> 7;
        int bf = k & (NBUF - 1);

        if (k + 2 < cnt) {
            int un = u + 2;
            issue_item(sbase, (k + 2) & (NBUF - 1), un >> 7, (un & 127) * NTILE);
            asm volatile("cp.async.wait_group 2;" ::: "memory");
        } else if (k + 1 < cnt) {
            asm volatile("cp.async.wait_group 1;" ::: "memory");
        } else {
            asm volatile("cp.async.wait_group 0;" ::: "memory");
        }
        __syncthreads();   // single barrier per item (4-buffer safety)

        // ---- 3-term GEMM: per kstep, 3 passes of 16 independent HMMAs
        float d[2][8][4];
        #pragma unroll
        for (int mt = 0; mt < 2; mt++)
            #pragma unroll
            for (int jb = 0; jb < 8; jb++)
                #pragma unroll
                for (int q = 0; q < 4; q++) d[mt][jb][q] = 0.f;

        u32 bhbase = sbase + (u32)bf * BUFSZ + boff;
        u32 blbase = bhbase + BTERM;
        #pragma unroll
        for (int ks = 0; ks < 6; ks++) {
            u32 bh[16], bl[16];
            #pragma unroll
            for (int jp = 0; jp < 4; jp++) {
                LDSM4(bh[jp*4+0], bh[jp*4+1], bh[jp*4+2], bh[jp*4+3],
                      bhbase + jp * (16 * BSTR) + ks * 32);
                LDSM4(bl[jp*4+0], bl[jp*4+1], bl[jp*4+2], bl[jp*4+3],
                      blbase + jp * (16 * BSTR) + ks * 32);
            }
            // pass A: Ah x Bh  (16 independent accumulators)
            #pragma unroll
            for (int mt = 0; mt < 2; mt++) {
                int o = ks * 8 + mt * 4;
                #pragma unroll
                for (int jp = 0; jp < 4; jp++) {
                    MMA16816(d[mt][2*jp],   Ah[o], Ah[o+1], Ah[o+2], Ah[o+3],
                             bh[jp*4+0], bh[jp*4+1]);
                    MMA16816(d[mt][2*jp+1], Ah[o], Ah[o+1], Ah[o+2], Ah[o+3],
                             bh[jp*4+2], bh[jp*4+3]);
                }
            }
            // pass B: Ah x Bl
            #pragma unroll
            for (int mt = 0; mt < 2; mt++) {
                int o = ks * 8 + mt * 4;
                #pragma unroll
                for (int jp = 0; jp < 4; jp++) {
                    MMA16816(d[mt][2*jp],   Ah[o], Ah[o+1], Ah[o+2], Ah[o+3],
                             bl[jp*4+0], bl[jp*4+1]);
                    MMA16816(d[mt][2*jp+1], Ah[o], Ah[o+1], Ah[o+2], Ah[o+3],
                             bl[jp*4+2], bl[jp*4+3]);
                }
            }
            // pass C: Al x Bh
            #pragma unroll
            for (int mt = 0; mt < 2; mt++) {
                int o = ks * 8 + mt * 4;
                #pragma unroll
                for (int jp = 0; jp < 4; jp++) {
                    MMA16816(d[mt][2*jp],   Al[o], Al[o+1], Al[o+2], Al[o+3],
                             bh[jp*4+0], bh[jp*4+1]);
                    MMA16816(d[mt][2*jp+1], Al[o], Al[o+1], Al[o+2], Al[o+3],
                             bh[jp*4+2], bh[jp*4+3]);
                }
            }
        }

        // ---- accumulate running min in registers (+a2)
        const float* a2sh = (const float*)(smem + SM_A2 + bf * 256);
        #pragma unroll
        for (int mt = 0; mt < 2; mt++) {
            float m0 = mm[mt][0], m1 = mm[mt][1];
            #pragma unroll
            for (int jb = 0; jb < 8; jb++) {
                float aa0 = a2sh[jb * 8 + tg * 2];
                float aa1 = a2sh[jb * 8 + tg * 2 + 1];
                m0 = fminf(m0, fminf(d[mt][jb][0] + aa0, d[mt][jb][1] + aa1));
                m1 = fminf(m1, fminf(d[mt][jb][2] + aa0, d[mt][jb][3] + aa1));
            }
            mm[mt][0] = m0; mm[mt][1] = m1;
        }

        // ---- flush at batch boundary or range end
        bool fl = (k == cnt - 1) || (((u + 1) >> 7) != b);
        if (fl) {
            #pragma unroll
            for (int mt = 0; mt < 2; mt++) {
                float m0 = mm[mt][0], m1 = mm[mt][1];
                m0 = fminf(m0, __shfl_xor_sync(0xFFFFFFFFu, m0, 1));
                m0 = fminf(m0, __shfl_xor_sync(0xFFFFFFFFu, m0, 2));
                m1 = fminf(m1, __shfl_xor_sync(0xFFFFFFFFu, m1, 1));
                m1 = fminf(m1, __shfl_xor_sync(0xFFFFFFFFu, m1, 2));
                if (tg == 0) {
                    int srow = warp * 32 + mt * 16 + g;
                    atomicMin(&g_amin[b * PNS + srow],     fenc(m0));
                    atomicMin(&g_amin[b * PNS + srow + 8], fenc(m1));
                }
                mm[mt][0] = 3.4e38f; mm[mt][1] = 3.4e38f;
            }
        }
    }

    // ---- Fused finish: last CTA to arrive writes the output
    __threadfence();
    __shared__ u32 s_rank;
    if (tid == 0) s_rank = atomicAdd(&g_done, 1u);
    __syncthreads();
    if (s_rank == gridDim.x - 1) {
        __threadfence();
        for (int i = tid; i < PB * PNS; i += THREADS) {
            u32 enc = __ldcg(&g_amin[i]);
            out[i] = (fdec(enc) + g_k2[i & (PNS - 1)]) * (1.0f / (float)PLS);
        }
    }
}

// ---------------------------------------------------------------------------
extern "C" void kernel_launch(void* const* d_in, const int* in_sizes, int n_in,
                              void* d_out, int out_size) {
    const float* data = (const float*)d_in[0];   // [32, 8192, 3]
    const float* ker  = (const float*)d_in[1];   // [256, 32, 3]
    float* out = (float*)d_out;                  // [32, 256]

    cudaFuncSetAttribute(mma_main_kernel,
                         cudaFuncAttributeMaxDynamicSharedMemorySize, SM_TOT);
    int dev = 0, nsm = 148;
    cudaGetDevice(&dev);
    cudaDeviceGetAttribute(&nsm, cudaDevAttrMultiProcessorCount, dev);
    if (nsm > NITEMS) nsm = NITEMS;

    prep1_kernel<<<(PB * PT + 255) / 256, 256>>>(data, ker);
    {
        int njobs = 8 * PB * (PTF / 8);
        if (njobs < PB * PT) njobs = PB * PT;
        prep2_kernel<<<(njobs + 255) / 256, 256>>>(data);
    }

    mma_main_kernel<<<nsm, THREADS, SM_TOT>>>(out);
}

// round 16
// speedup vs baseline: 1.3695x; 1.3695x over previous
#include <cuda_runtime.h>
#include <cuda_fp16.h>

// Problem constants
#define PB   32
#define PT   8192
#define PC   3
#define PLS  32
#define PNS  256
#define PW   (PT - PLS + 1)        // 8161

#define KF      96                 // K = LS*C
#define KPAD    128                // global K row pad (u16 elements)
#define NTILE   64                 // windows per item
#define WTILES  (PT / NTILE)       // 128
#define NITEMS  (PB * WTILES)      // 4096
#define THREADS 512                // 16 warps, 4 per SMSP

#define FLATN   (PT * PC)          // 24576
#define PTF     (FLATN + 96)       // phase-array padded length (24672)

#define BSTR    208                // B row stride bytes (104 fp16, conflict-free)
#define BUFSZ   (64 * BSTR)        // 13312 (single term now)
#define NBUF    4
#define SM_A2   (NBUF * BUFSZ)     // 53248
#define SM_TOT  (SM_A2 + NBUF * 256)  // 54272

typedef unsigned int u32;
typedef unsigned short u16;

// Device scratch (allocations forbidden)
__device__ __align__(16) u16 g_xf[8 * PB * PTF];    // 8 phase-shifted flat fp16(data)
__device__ __align__(16) u16 g_khi[PNS * KPAD];     // fp16(-2k) hi
__device__ __align__(16) u16 g_klo[PNS * KPAD];     // fp16 lo residual
__device__ float g_d2[PB * PT];
__device__ float g_a2[PB * PT];                     // padded; >=PW poisoned
__device__ float g_k2[PNS];
__device__ u32   g_amin[PB * PNS];
__device__ u32   g_done;

// ---------------------------------------------------------------------------
__device__ __forceinline__ u32 smem_u32(const void* p) {
    u32 a; asm("{ .reg .u64 t; cvta.to.shared.u64 t, %1; cvt.u32.u64 %0, t; }"
               : "=r"(a) : "l"(p));
    return a;
}
__device__ __forceinline__ u32 fenc(float f) {
    u32 u = __float_as_uint(f);
    return (u & 0x80000000u) ? ~u : (u | 0x80000000u);
}
__device__ __forceinline__ float fdec(u32 u) {
    u32 b = (u & 0x80000000u) ? (u & 0x7FFFFFFFu) : ~u;
    return __uint_as_float(b);
}
// pack two fp16(x) into u32
__device__ __forceinline__ u32 packh2(float v0, float v1) {
    __half h0 = __float2half_rn(v0);
    __half h1 = __float2half_rn(v1);
    return (u32)__half_as_ushort(h0) | ((u32)__half_as_ushort(h1) << 16);
}

#define LDSM4(r0, r1, r2, r3, addr) \
    asm volatile("ldmatrix.sync.aligned.m8n8.x4.shared.b16 {%0,%1,%2,%3}, [%4];" \
        : "=r"(r0), "=r"(r1), "=r"(r2), "=r"(r3) : "r"(addr))

#define MMA16816(d, a0, a1, a2, a3, b0, b1) \
    asm volatile("mma.sync.aligned.m16n8k16.row.col.f32.f16.f16.f32 " \
        "{%0,%1,%2,%3}, {%4,%5,%6,%7}, {%8,%9}, {%0,%1,%2,%3};" \
        : "+f"((d)[0]), "+f"((d)[1]), "+f"((d)[2]), "+f"((d)[3]) \
        : "r"(a0), "r"(a1), "r"(a2), "r"(a3), "r"(b0), "r"(b1))

#define CPASYNC16(dst, src) \
    asm volatile("cp.async.cg.shared.global [%0], [%1], 16;" :: "r"(dst), "l"(src))
#define CPASYNC4(dst, src) \
    asm volatile("cp.async.ca.shared.global [%0], [%1], 4;" :: "r"(dst), "l"(src))

// ---------------------------------------------------------------------------
// prep1: d2, K(-2k) fp16 hi/lo, amin init, warp-parallel k2, done counter
__global__ void prep1_kernel(const float* __restrict__ data,
                             const float* __restrict__ ker) {
    int i = blockIdx.x * blockDim.x + threadIdx.x;
    if (i < PB * PT) {
        const float* p = data + (size_t)i * 3;
        float x0 = p[0], x1 = p[1], x2 = p[2];
        g_d2[i] = x0 * x0 + x1 * x1 + x2 * x2;
    }
    if (i < PNS * PLS) {
        int s = i / PLS, l = i % PLS;
        #pragma unroll
        for (int c = 0; c < 3; c++) {
            float v = -2.f * ker[i * 3 + c];
            __half hi = __float2half_rn(v);
            __half lo = __float2half_rn(v - __half2float(hi));
            g_khi[s * KPAD + l * 3 + c] = __half_as_ushort(hi);
            g_klo[s * KPAD + l * 3 + c] = __half_as_ushort(lo);
        }
    }
    if (i < PB * PNS) g_amin[i] = 0xFFFFFFFFu;
    if (i < PNS * 32) {
        int s = i >> 5, lane = i & 31;
        const float* kp = ker + s * KF + lane * 3;
        float v0 = kp[0], v1 = kp[1], v2 = kp[2];
        float k2 = v0 * v0 + v1 * v1 + v2 * v2;
        #pragma unroll
        for (int off = 16; off > 0; off >>= 1)
            k2 += __shfl_xor_sync(0xFFFFFFFFu, k2, off);
        if (lane == 0) g_k2[s] = k2;
    }
    if (i == 0) g_done = 0u;
}

// prep2: fp16 phase arrays (uint4 = 8 elements/thread) + a2 from d2
__global__ void prep2_kernel(const float* __restrict__ data) {
    const int HP4 = PTF / 8;            // uint4 per (p,b) = 3084
    int j = blockIdx.x * blockDim.x + threadIdx.x;
    if (j < 8 * PB * HP4) {
        int i4 = j % HP4;
        int r  = j / HP4;               // = p*PB + b
        int b  = r % PB;
        int p  = r / PB;
        int e0 = 8 * i4 + p;
        const float* db = data + (size_t)b * FLATN;
        float v[8];
        #pragma unroll
        for (int m = 0; m < 8; m++) {
            int em = e0 + m;
            v[m] = (em < FLATN) ? __ldg(db + em) : 0.f;
        }
        uint4 H;
        H.x = packh2(v[0], v[1]);
        H.y = packh2(v[2], v[3]);
        H.z = packh2(v[4], v[5]);
        H.w = packh2(v[6], v[7]);
        ((uint4*)g_xf)[r * HP4 + i4] = H;
    }
    if (j < PB * PT) {
        int b = j / PT, w = j % PT;
        float s = 1e30f;
        if (w < PW) {
            const float* d = g_d2 + b * PT + w;
            s = 0.f;
            #pragma unroll
            for (int q = 0; q < PLS; q++) s += d[q];
        }
        g_a2[j] = s;
    }
}

// ---------------------------------------------------------------------------
// issue cp.async group for one item: 64 rows x 12 quads (single term) + a2
__device__ __forceinline__ void issue_item(u32 sbase, int buf, int b, int w0) {
    int tid = threadIdx.x;
    u32 bufbase = sbase + (u32)buf * BUFSZ;
    {   // rep 0: c = 0..511
        int c = tid;
        int row = c / 12, q = c - row * 12;
        int E = 3 * (w0 + row), p = E & 7;
        const u16* src = g_xf + (size_t)(p * PB + b) * PTF + (E - p) + q * 8;
        u32 dst = bufbase + (u32)row * BSTR + (u32)q * 16;
        CPASYNC16(dst, src);
    }
    if (tid < 256) {   // rep 1: c = 512..767
        int c = tid + 512;
        int row = c / 12, q = c - row * 12;
        int E = 3 * (w0 + row), p = E & 7;
        const u16* src = g_xf + (size_t)(p * PB + b) * PTF + (E - p) + q * 8;
        u32 dst = bufbase + (u32)row * BSTR + (u32)q * 16;
        CPASYNC16(dst, src);
    }
    if (tid < NTILE) {
        const float* src = g_a2 + (size_t)b * PT + w0 + tid;
        u32 dst = sbase + SM_A2 + (u32)buf * 256 + (u32)tid * 4;
        CPASYNC4(dst, src);
    }
    asm volatile("cp.async.commit_group;" ::: "memory");
}

// ---------------------------------------------------------------------------
// Main: 16 warps (M=16/warp), 2-term fp16 GEMM, 4-buffer ring, deferred min.
__global__ __launch_bounds__(THREADS, 1) void mma_main_kernel(
        float* __restrict__ out) {
    extern __shared__ __align__(16) char smem[];
    u32 sbase = smem_u32(smem);
    int tid  = threadIdx.x;
    int lane = tid & 31;
    int warp = tid >> 5;                 // 0..15 -> M rows warp*16..+15
    int g    = lane >> 2;                // 0..7
    int tg   = lane & 3;                 // 0..3

    // ---- Persistent A fragments (m16k16 layout), loaded once via LDG
    u32 Ah[24], Al[24];                  // [ks*4 + q]
    {
        int r0 = warp * 16 + g;
        #pragma unroll
        for (int ks = 0; ks < 6; ks++) {
            int col = ks * 16 + tg * 2;
            const u16* ph = g_khi + (size_t)r0 * KPAD + col;
            const u16* pl = g_klo + (size_t)r0 * KPAD + col;
            int o = ks * 4;
            Ah[o + 0] = *(const u32*)(ph);
            Ah[o + 1] = *(const u32*)(ph + 8 * KPAD);
            Ah[o + 2] = *(const u32*)(ph + 8);
            Ah[o + 3] = *(const u32*)(ph + 8 * KPAD + 8);
            Al[o + 0] = *(const u32*)(pl);
            Al[o + 1] = *(const u32*)(pl + 8 * KPAD);
            Al[o + 2] = *(const u32*)(pl + 8);
            Al[o + 3] = *(const u32*)(pl + 8 * KPAD + 8);
        }
    }

    // ldmatrix B per-thread offset (proven mapping)
    int ti = lane >> 3, l8 = lane & 7;
    u32 boff = (u32)((((ti >> 1) * 8 + l8) * BSTR) + (ti & 1) * 16);

    // ---- contiguous item range for this CTA
    int G    = gridDim.x;
    int base = NITEMS / G, rem = NITEMS % G;
    int cta  = blockIdx.x;
    int lo   = cta * base + (cta < rem ? cta : rem);
    int cnt  = base + (cta < rem ? 1 : 0);

    // ---- prologue: prefetch up to 2 items
    if (cnt > 0) issue_item(sbase, 0, lo >> 7,        (lo & 127) * NTILE);
    if (cnt > 1) issue_item(sbase, 1, (lo + 1) >> 7, ((lo + 1) & 127) * NTILE);

    float mm0 = 3.4e38f, mm1 = 3.4e38f;

    for (int k = 0; k < cnt; k++) {
        int u  = lo + k;
        int b  = u >> 7;
        int bf = k & (NBUF - 1);

        if (k + 2 < cnt) {
            int un = u + 2;
            issue_item(sbase, (k + 2) & (NBUF - 1), un >> 7, (un & 127) * NTILE);
            asm volatile("cp.async.wait_group 2;" ::: "memory");
        } else if (k + 1 < cnt) {
            asm volatile("cp.async.wait_group 1;" ::: "memory");
        } else {
            asm volatile("cp.async.wait_group 0;" ::: "memory");
        }
        __syncthreads();   // single barrier per item (4-buffer safety)

        // ---- 2-term GEMM on buf: D = Ah*B + Al*B
        float d[8][4];
        #pragma unroll
        for (int jb = 0; jb < 8; jb++)
            #pragma unroll
            for (int q = 0; q < 4; q++) d[jb][q] = 0.f;

        u32 bhbase = sbase + (u32)bf * BUFSZ + boff;
        #pragma unroll
        for (int ks = 0; ks < 6; ks++) {
            u32 bh[16];
            #pragma unroll
            for (int jp = 0; jp < 4; jp++)
                LDSM4(bh[jp*4+0], bh[jp*4+1], bh[jp*4+2], bh[jp*4+3],
                      bhbase + jp * (16 * BSTR) + ks * 32);
            int o = ks * 4;
            #pragma unroll
            for (int jp = 0; jp < 4; jp++) {
                MMA16816(d[2*jp],   Ah[o], Ah[o+1], Ah[o+2], Ah[o+3],
                         bh[jp*4+0], bh[jp*4+1]);
                MMA16816(d[2*jp+1], Ah[o], Ah[o+1], Ah[o+2], Ah[o+3],
                         bh[jp*4+2], bh[jp*4+3]);
            }
            #pragma unroll
            for (int jp = 0; jp < 4; jp++) {
                MMA16816(d[2*jp],   Al[o], Al[o+1], Al[o+2], Al[o+3],
                         bh[jp*4+0], bh[jp*4+1]);
                MMA16816(d[2*jp+1], Al[o], Al[o+1], Al[o+2], Al[o+3],
                         bh[jp*4+2], bh[jp*4+3]);
            }
        }

        // ---- accumulate running min in registers (+a2)
        const float* a2sh = (const float*)(smem + SM_A2 + bf * 256);
        {
            float m0 = mm0, m1 = mm1;
            #pragma unroll
            for (int jb = 0; jb < 8; jb++) {
                float aa0 = a2sh[jb * 8 + tg * 2];
                float aa1 = a2sh[jb * 8 + tg * 2 + 1];
                m0 = fminf(m0, fminf(d[jb][0] + aa0, d[jb][1] + aa1));
                m1 = fminf(m1, fminf(d[jb][2] + aa0, d[jb][3] + aa1));
            }
            mm0 = m0; mm1 = m1;
        }

        // ---- flush at batch boundary or range end
        bool fl = (k == cnt - 1) || (((u + 1) >> 7) != b);
        if (fl) {
            float m0 = mm0, m1 = mm1;
            m0 = fminf(m0, __shfl_xor_sync(0xFFFFFFFFu, m0, 1));
            m0 = fminf(m0, __shfl_xor_sync(0xFFFFFFFFu, m0, 2));
            m1 = fminf(m1, __shfl_xor_sync(0xFFFFFFFFu, m1, 1));
            m1 = fminf(m1, __shfl_xor_sync(0xFFFFFFFFu, m1, 2));
            if (tg == 0) {
                int srow = warp * 16 + g;
                atomicMin(&g_amin[b * PNS + srow],     fenc(m0));
                atomicMin(&g_amin[b * PNS + srow + 8], fenc(m1));
            }
            mm0 = 3.4e38f; mm1 = 3.4e38f;
        }
    }

    // ---- Fused finish: last CTA to arrive writes the output
    __threadfence();
    __shared__ u32 s_rank;
    if (tid == 0) s_rank = atomicAdd(&g_done, 1u);
    __syncthreads();
    if (s_rank == gridDim.x - 1) {
        __threadfence();
        for (int i = tid; i < PB * PNS; i += THREADS) {
            u32 enc = __ldcg(&g_amin[i]);
            out[i] = (fdec(enc) + g_k2[i & (PNS - 1)]) * (1.0f / (float)PLS);
        }
    }
}

// ---------------------------------------------------------------------------
extern "C" void kernel_launch(void* const* d_in, const int* in_sizes, int n_in,
                              void* d_out, int out_size) {
    const float* data = (const float*)d_in[0];   // [32, 8192, 3]
    const float* ker  = (const float*)d_in[1];   // [256, 32, 3]
    float* out = (float*)d_out;                  // [32, 256]

    cudaFuncSetAttribute(mma_main_kernel,
                         cudaFuncAttributeMaxDynamicSharedMemorySize, SM_TOT);
    int dev = 0, nsm = 148;
    cudaGetDevice(&dev);
    cudaDeviceGetAttribute(&nsm, cudaDevAttrMultiProcessorCount, dev);
    if (nsm > NITEMS) nsm = NITEMS;

    prep1_kernel<<<(PB * PT + 255) / 256, 256>>>(data, ker);
    {
        int njobs = 8 * PB * (PTF / 8);
        if (njobs < PB * PT) njobs = PB * PT;
        prep2_kernel<<<(njobs + 255) / 256, 256>>>(data);
    }

    mma_main_kernel<<<nsm, THREADS, SM_TOT>>>(out);
}

// round 17
// speedup vs baseline: 1.8612x; 1.3590x over previous
#include <cuda_runtime.h>
#include <cuda_fp16.h>

// Problem constants
#define PB   32
#define PT   8192
#define PC   3
#define PLS  32
#define PNS  256
#define PW   (PT - PLS + 1)        // 8161

#define KF      96                 // K = LS*C
#define KPAD    128                // global K row pad (u16 elements)
#define NTILE   64                 // windows per item
#define WTILES  (PT / NTILE)       // 128
#define NITEMS  (PB * WTILES)      // 4096
#define THREADS 512                // 16 warps, 4 per SMSP

#define FLATN   (PT * PC)          // 24576
#define PTF     (FLATN + 96)       // phase-array padded length (24672)

#define BSTR    208                // B row stride bytes (104 fp16, conflict-free)
#define BUFSZ   (64 * BSTR)        // 13312
#define NBUF    4
#define SM_A2   (NBUF * BUFSZ)     // 53248
#define SM_TOT  (SM_A2 + NBUF * 256)  // 54272

typedef unsigned int u32;
typedef unsigned short u16;

// Device scratch (allocations forbidden)
__device__ __align__(16) u16 g_xf[8 * PB * PTF];    // 8 phase-shifted flat fp16(data)
__device__ __align__(16) u16 g_khi[PNS * KPAD];     // fp16(-2k)
__device__ float g_d2[PB * PT];
__device__ float g_a2[PB * PT];                     // padded; >=PW poisoned
__device__ float g_k2[PNS];
__device__ u32   g_amin[PB * PNS];
__device__ u32   g_done;

// ---------------------------------------------------------------------------
__device__ __forceinline__ u32 smem_u32(const void* p) {
    u32 a; asm("{ .reg .u64 t; cvta.to.shared.u64 t, %1; cvt.u32.u64 %0, t; }"
               : "=r"(a) : "l"(p));
    return a;
}
__device__ __forceinline__ u32 fenc(float f) {
    u32 u = __float_as_uint(f);
    return (u & 0x80000000u) ? ~u : (u | 0x80000000u);
}
__device__ __forceinline__ float fdec(u32 u) {
    u32 b = (u & 0x80000000u) ? (u & 0x7FFFFFFFu) : ~u;
    return __uint_as_float(b);
}
// pack two fp16(x) into u32
__device__ __forceinline__ u32 packh2(float v0, float v1) {
    __half h0 = __float2half_rn(v0);
    __half h1 = __float2half_rn(v1);
    return (u32)__half_as_ushort(h0) | ((u32)__half_as_ushort(h1) << 16);
}

#define LDSM4(r0, r1, r2, r3, addr) \
    asm volatile("ldmatrix.sync.aligned.m8n8.x4.shared.b16 {%0,%1,%2,%3}, [%4];" \
        : "=r"(r0), "=r"(r1), "=r"(r2), "=r"(r3) : "r"(addr))

#define MMA16816(d, a0, a1, a2, a3, b0, b1) \
    asm volatile("mma.sync.aligned.m16n8k16.row.col.f32.f16.f16.f32 " \
        "{%0,%1,%2,%3}, {%4,%5,%6,%7}, {%8,%9}, {%0,%1,%2,%3};" \
        : "+f"((d)[0]), "+f"((d)[1]), "+f"((d)[2]), "+f"((d)[3]) \
        : "r"(a0), "r"(a1), "r"(a2), "r"(a3), "r"(b0), "r"(b1))

#define CPASYNC16(dst, src) \
    asm volatile("cp.async.cg.shared.global [%0], [%1], 16;" :: "r"(dst), "l"(src))
#define CPASYNC4(dst, src) \
    asm volatile("cp.async.ca.shared.global [%0], [%1], 4;" :: "r"(dst), "l"(src))

// ---------------------------------------------------------------------------
// prep1: d2, K(-2k) fp16, amin init, warp-parallel k2, done counter
__global__ void prep1_kernel(const float* __restrict__ data,
                             const float* __restrict__ ker) {
    int i = blockIdx.x * blockDim.x + threadIdx.x;
    if (i < PB * PT) {
        const float* p = data + (size_t)i * 3;
        float x0 = p[0], x1 = p[1], x2 = p[2];
        g_d2[i] = x0 * x0 + x1 * x1 + x2 * x2;
    }
    if (i < PNS * PLS) {
        int s = i / PLS, l = i % PLS;
        #pragma unroll
        for (int c = 0; c < 3; c++) {
            float v = -2.f * ker[i * 3 + c];
            g_khi[s * KPAD + l * 3 + c] = __half_as_ushort(__float2half_rn(v));
        }
    }
    if (i < PB * PNS) g_amin[i] = 0xFFFFFFFFu;
    if (i < PNS * 32) {
        int s = i >> 5, lane = i & 31;
        const float* kp = ker + s * KF + lane * 3;
        float v0 = kp[0], v1 = kp[1], v2 = kp[2];
        float k2 = v0 * v0 + v1 * v1 + v2 * v2;
        #pragma unroll
        for (int off = 16; off > 0; off >>= 1)
            k2 += __shfl_xor_sync(0xFFFFFFFFu, k2, off);
        if (lane == 0) g_k2[s] = k2;
    }
    if (i == 0) g_done = 0u;
}

// prep2: fp16 phase arrays (uint4 = 8 elements/thread) + a2 from d2
__global__ void prep2_kernel(const float* __restrict__ data) {
    const int HP4 = PTF / 8;            // uint4 per (p,b) = 3084
    int j = blockIdx.x * blockDim.x + threadIdx.x;
    if (j < 8 * PB * HP4) {
        int i4 = j % HP4;
        int r  = j / HP4;               // = p*PB + b
        int b  = r % PB;
        int p  = r / PB;
        int e0 = 8 * i4 + p;
        const float* db = data + (size_t)b * FLATN;
        float v[8];
        #pragma unroll
        for (int m = 0; m < 8; m++) {
            int em = e0 + m;
            v[m] = (em < FLATN) ? __ldg(db + em) : 0.f;
        }
        uint4 H;
        H.x = packh2(v[0], v[1]);
        H.y = packh2(v[2], v[3]);
        H.z = packh2(v[4], v[5]);
        H.w = packh2(v[6], v[7]);
        ((uint4*)g_xf)[r * HP4 + i4] = H;
    }
    if (j < PB * PT) {
        int b = j / PT, w = j % PT;
        float s = 1e30f;
        if (w < PW) {
            const float* d = g_d2 + b * PT + w;
            s = 0.f;
            #pragma unroll
            for (int q = 0; q < PLS; q++) s += d[q];
        }
        g_a2[j] = s;
    }
}

// ---------------------------------------------------------------------------
// issue cp.async group for one item: 64 rows x 12 quads + a2
__device__ __forceinline__ void issue_item(u32 sbase, int buf, int b, int w0) {
    int tid = threadIdx.x;
    u32 bufbase = sbase + (u32)buf * BUFSZ;
    {   // c = 0..511
        int c = tid;
        int row = c / 12, q = c - row * 12;
        int E = 3 * (w0 + row), p = E & 7;
        const u16* src = g_xf + (size_t)(p * PB + b) * PTF + (E - p) + q * 8;
        u32 dst = bufbase + (u32)row * BSTR + (u32)q * 16;
        CPASYNC16(dst, src);
    }
    if (tid < 256) {   // c = 512..767
        int c = tid + 512;
        int row = c / 12, q = c - row * 12;
        int E = 3 * (w0 + row), p = E & 7;
        const u16* src = g_xf + (size_t)(p * PB + b) * PTF + (E - p) + q * 8;
        u32 dst = bufbase + (u32)row * BSTR + (u32)q * 16;
        CPASYNC16(dst, src);
    }
    if (tid < NTILE) {
        const float* src = g_a2 + (size_t)b * PT + w0 + tid;
        u32 dst = sbase + SM_A2 + (u32)buf * 256 + (u32)tid * 4;
        CPASYNC4(dst, src);
    }
    asm volatile("cp.async.commit_group;" ::: "memory");
}

// ---------------------------------------------------------------------------
// Main: 16 warps (M=16/warp), single-term fp16 GEMM, 4-buffer ring, deferred min.
__global__ __launch_bounds__(THREADS, 1) void mma_main_kernel(
        float* __restrict__ out) {
    extern __shared__ __align__(16) char smem[];
    u32 sbase = smem_u32(smem);
    int tid  = threadIdx.x;
    int lane = tid & 31;
    int warp = tid >> 5;                 // 0..15 -> M rows warp*16..+15
    int g    = lane >> 2;                // 0..7
    int tg   = lane & 3;                 // 0..3

    // ---- Persistent A fragments (m16k16 layout), loaded once via LDG
    u32 Ah[24];                          // [ks*4 + q]
    {
        int r0 = warp * 16 + g;
        #pragma unroll
        for (int ks = 0; ks < 6; ks++) {
            int col = ks * 16 + tg * 2;
            const u16* ph = g_khi + (size_t)r0 * KPAD + col;
            int o = ks * 4;
            Ah[o + 0] = *(const u32*)(ph);
            Ah[o + 1] = *(const u32*)(ph + 8 * KPAD);
            Ah[o + 2] = *(const u32*)(ph + 8);
            Ah[o + 3] = *(const u32*)(ph + 8 * KPAD + 8);
        }
    }

    // ldmatrix B per-thread offset (proven mapping)
    int ti = lane >> 3, l8 = lane & 7;
    u32 boff = (u32)((((ti >> 1) * 8 + l8) * BSTR) + (ti & 1) * 16);

    // ---- contiguous item range for this CTA
    int G    = gridDim.x;
    int base = NITEMS / G, rem = NITEMS % G;
    int cta  = blockIdx.x;
    int lo   = cta * base + (cta < rem ? cta : rem);
    int cnt  = base + (cta < rem ? 1 : 0);

    // ---- prologue: prefetch up to 2 items
    if (cnt > 0) issue_item(sbase, 0, lo >> 7,        (lo & 127) * NTILE);
    if (cnt > 1) issue_item(sbase, 1, (lo + 1) >> 7, ((lo + 1) & 127) * NTILE);

    float mm0 = 3.4e38f, mm1 = 3.4e38f;

    for (int k = 0; k < cnt; k++) {
        int u  = lo + k;
        int b  = u >> 7;
        int bf = k & (NBUF - 1);

        if (k + 2 < cnt) {
            int un = u + 2;
            issue_item(sbase, (k + 2) & (NBUF - 1), un >> 7, (un & 127) * NTILE);
            asm volatile("cp.async.wait_group 2;" ::: "memory");
        } else if (k + 1 < cnt) {
            asm volatile("cp.async.wait_group 1;" ::: "memory");
        } else {
            asm volatile("cp.async.wait_group 0;" ::: "memory");
        }
        __syncthreads();   // single barrier per item (4-buffer safety)

        // ---- single-term GEMM on buf: D = A*B
        float d[8][4];
        #pragma unroll
        for (int jb = 0; jb < 8; jb++)
            #pragma unroll
            for (int q = 0; q < 4; q++) d[jb][q] = 0.f;

        u32 bhbase = sbase + (u32)bf * BUFSZ + boff;
        #pragma unroll
        for (int ks = 0; ks < 6; ks++) {
            u32 bh[16];
            #pragma unroll
            for (int jp = 0; jp < 4; jp++)
                LDSM4(bh[jp*4+0], bh[jp*4+1], bh[jp*4+2], bh[jp*4+3],
                      bhbase + jp * (16 * BSTR) + ks * 32);
            int o = ks * 4;
            #pragma unroll
            for (int jp = 0; jp < 4; jp++) {
                MMA16816(d[2*jp],   Ah[o], Ah[o+1], Ah[o+2], Ah[o+3],
                         bh[jp*4+0], bh[jp*4+1]);
                MMA16816(d[2*jp+1], Ah[o], Ah[o+1], Ah[o+2], Ah[o+3],
                         bh[jp*4+2], bh[jp*4+3]);
            }
        }

        // ---- accumulate running min in registers (+a2)
        const float* a2sh = (const float*)(smem + SM_A2 + bf * 256);
        {
            float m0 = mm0, m1 = mm1;
            #pragma unroll
            for (int jb = 0; jb < 8; jb++) {
                float aa0 = a2sh[jb * 8 + tg * 2];
                float aa1 = a2sh[jb * 8 + tg * 2 + 1];
                m0 = fminf(m0, fminf(d[jb][0] + aa0, d[jb][1] + aa1));
                m1 = fminf(m1, fminf(d[jb][2] + aa0, d[jb][3] + aa1));
            }
            mm0 = m0; mm1 = m1;
        }

        // ---- flush at batch boundary or range end
        bool fl = (k == cnt - 1) || (((u + 1) >> 7) != b);
        if (fl) {
            float m0 = mm0, m1 = mm1;
            m0 = fminf(m0, __shfl_xor_sync(0xFFFFFFFFu, m0, 1));
            m0 = fminf(m0, __shfl_xor_sync(0xFFFFFFFFu, m0, 2));
            m1 = fminf(m1, __shfl_xor_sync(0xFFFFFFFFu, m1, 1));
            m1 = fminf(m1, __shfl_xor_sync(0xFFFFFFFFu, m1, 2));
            if (tg == 0) {
                int srow = warp * 16 + g;
                atomicMin(&g_amin[b * PNS + srow],     fenc(m0));
                atomicMin(&g_amin[b * PNS + srow + 8], fenc(m1));
            }
            mm0 = 3.4e38f; mm1 = 3.4e38f;
        }
    }

    // ---- Fused finish: last CTA to arrive writes the output
    __threadfence();
    __shared__ u32 s_rank;
    if (tid == 0) s_rank = atomicAdd(&g_done, 1u);
    __syncthreads();
    if (s_rank == gridDim.x - 1) {
        __threadfence();
        for (int i = tid; i < PB * PNS; i += THREADS) {
            u32 enc = __ldcg(&g_amin[i]);
            out[i] = (fdec(enc) + g_k2[i & (PNS - 1)]) * (1.0f / (float)PLS);
        }
    }
}

// ---------------------------------------------------------------------------
extern "C" void kernel_launch(void* const* d_in, const int* in_sizes, int n_in,
                              void* d_out, int out_size) {
    const float* data = (const float*)d_in[0];   // [32, 8192, 3]
    const float* ker  = (const float*)d_in[1];   // [256, 32, 3]
    float* out = (float*)d_out;                  // [32, 256]

    cudaFuncSetAttribute(mma_main_kernel,
                         cudaFuncAttributeMaxDynamicSharedMemorySize, SM_TOT);
    int dev = 0, nsm = 148;
    cudaGetDevice(&dev);
    cudaDeviceGetAttribute(&nsm, cudaDevAttrMultiProcessorCount, dev);
    if (nsm > NITEMS) nsm = NITEMS;

    prep1_kernel<<<(PB * PT + 255) / 256, 256>>>(data, ker);
    {
        int njobs = 8 * PB * (PTF / 8);
        if (njobs < PB * PT) njobs = PB * PT;
        prep2_kernel<<<(njobs + 255) / 256, 256>>>(data);
    }

    mma_main_kernel<<<nsm, THREADS, SM_TOT>>>(out);
}